// round 3
// baseline (speedup 1.0000x reference)
#include <cuda_runtime.h>
#include <math_constants.h>

#define NB 128
#define N 1024
#define NITERS 20
#define GROUP 16
#define NGROUPS (NB / GROUP)
#define RPB 16                 // rows per block (band held in SMEM)
#define BPB (N / RPB)          // 64 blocks per batch
#define THREADS 512
#define LOG2E 1.44269504088896340736f

// s is stored in LOG2 domain: s2 = (log_alpha + gumbel)/TEMP * log2(e).
// R, C are log2-domain normalizers. exp() -> exp2f (bare MUFU.EX2).
static __device__ float g_s[(size_t)NB * N * N];          // 512 MB
static __device__ float g_R[NB * N];
static __device__ float g_C[NB * N];
static __device__ float g_part[GROUP][BPB][N];            // col partials, 4 MB
static __device__ unsigned g_cnt[GROUP];                  // last-block counters

// ---------------------------------------------------------------------------
// Init: s2 = (la + gumbel)/TEMP * log2e, zero C for the group.
// ---------------------------------------------------------------------------
__global__ void __launch_bounds__(256) gs_init(const float* __restrict__ la,
                                               const float* __restrict__ noise,
                                               int b0) {
    const float EPS = 1e-20f;
    size_t tid = (size_t)blockIdx.x * 256 + threadIdx.x;
    size_t e = (size_t)b0 * N * N + tid * 4;
    float4 a = *reinterpret_cast<const float4*>(la + e);
    float4 u = *reinterpret_cast<const float4*>(noise + e);
    const float SC = 10.0f * LOG2E;   // 1/TEMP * log2e
    float4 s;
    s.x = (a.x - logf(EPS - logf(u.x + EPS))) * SC;
    s.y = (a.y - logf(EPS - logf(u.y + EPS))) * SC;
    s.z = (a.z - logf(EPS - logf(u.z + EPS))) * SC;
    s.w = (a.w - logf(EPS - logf(u.w + EPS))) * SC;
    *reinterpret_cast<float4*>(g_s + e) = s;
    if (tid < (size_t)GROUP * N) g_C[(size_t)b0 * N + tid] = 0.0f;
}

// ---------------------------------------------------------------------------
// Fused Sinkhorn iteration (row normalize + col normalize), ONE read of s.
//   pass1 (warp-per-row): e_ij = exp2(s - C_prev - R_prev)  [<= 1, no max
//          needed since C_prev = LSE_i(s - R_prev) >= s - R_prev];
//          rowsum -> R_new = R_prev + log2(rowsum), inv = 1/rowsum.
//          Band of e stays in SMEM.
//   pass2: col partials  sum_i e_ij * inv_i  (identity:
//          exp2(s - R_new - C_prev) = e_ij / rowsum_i), written to fixed
//          per-block slots; deterministic last-block reduction finishes
//          C_new = C_prev + log2(colsum).
//   first=1 handles t=0 (C=0, unbounded s) with an exact per-row max via an
//   SMEM round-trip; pass2 is identical.
// ---------------------------------------------------------------------------
__global__ void __launch_bounds__(THREADS, 3) gs_iter(int b0, int first) {
    extern __shared__ float smem[];
    float* se   = smem;              // e band: RPB x N
    float* sc   = smem + RPB * N;    // C_prev: N
    float* sinv = sc + N;            // 1/rowsum: RPB

    int tid = threadIdx.x, lane = tid & 31, w = tid >> 5;
    int blocal = blockIdx.x / BPB;         // batch within group
    int blk    = blockIdx.x % BPB;         // block within batch
    int b = b0 + blocal;
    int row0 = blk * RPB;

    if (!first) {
        sc[tid]       = g_C[(size_t)b * N + tid];
        sc[tid + 512] = g_C[(size_t)b * N + tid + 512];
    } else {
        sc[tid] = 0.0f; sc[tid + 512] = 0.0f;
    }
    __syncthreads();

    // ---- pass 1: warp w owns row row0 + w ----
    const float4* __restrict__ srow =
        reinterpret_cast<const float4*>(g_s + ((size_t)b * N + row0 + w) * N);
    float4* erow = reinterpret_cast<float4*>(se + w * N);
    const float4* scv = reinterpret_cast<const float4*>(sc);

    float base, sum = 0.0f;
    if (first) {
        float m = -CUDART_INF_F;
#pragma unroll
        for (int k = 0; k < 8; k++) {
            float4 sv = srow[k * 32 + lane];
            erow[k * 32 + lane] = sv;
            m = fmaxf(m, fmaxf(fmaxf(sv.x, sv.y), fmaxf(sv.z, sv.w)));
        }
#pragma unroll
        for (int o = 16; o; o >>= 1) m = fmaxf(m, __shfl_xor_sync(~0u, m, o));
#pragma unroll
        for (int k = 0; k < 8; k++) {
            float4 x = erow[k * 32 + lane];
            float4 ev;
            ev.x = exp2f(x.x - m); ev.y = exp2f(x.y - m);
            ev.z = exp2f(x.z - m); ev.w = exp2f(x.w - m);
            erow[k * 32 + lane] = ev;
            sum += (ev.x + ev.y) + (ev.z + ev.w);
        }
        base = m;
    } else {
        float rprev = g_R[(size_t)b * N + row0 + w];
#pragma unroll
        for (int k = 0; k < 8; k++) {
            float4 sv = srow[k * 32 + lane];
            float4 cv = scv[k * 32 + lane];
            float4 ev;
            ev.x = exp2f(sv.x - cv.x - rprev);
            ev.y = exp2f(sv.y - cv.y - rprev);
            ev.z = exp2f(sv.z - cv.z - rprev);
            ev.w = exp2f(sv.w - cv.w - rprev);
            erow[k * 32 + lane] = ev;
            sum += (ev.x + ev.y) + (ev.z + ev.w);
        }
        base = rprev;
    }
#pragma unroll
    for (int o = 16; o; o >>= 1) sum += __shfl_xor_sync(~0u, sum, o);
    if (lane == 0) {
        g_R[(size_t)b * N + row0 + w] = base + __log2f(sum);
        sinv[w] = 1.0f / sum;
    }
    __syncthreads();

    // ---- pass 2: warp w owns cols [w*64, w*64+64), SMEM FMAs only ----
    int j0 = w * 64 + lane;
    float a0 = 0.0f, a1 = 0.0f;
#pragma unroll
    for (int i = 0; i < RPB; i++) {
        float iv = sinv[i];
        a0 = fmaf(se[i * N + j0], iv, a0);
        a1 = fmaf(se[i * N + j0 + 32], iv, a1);
    }
    g_part[blocal][blk][j0]      = a0;
    g_part[blocal][blk][j0 + 32] = a1;

    // ---- deterministic last-block column finalize ----
    __shared__ unsigned s_last;
    __threadfence();
    if (tid == 0) s_last = (atomicAdd(&g_cnt[blocal], 1u) == BPB - 1);
    __syncthreads();
    if (s_last) {
        __threadfence();
        for (int j = tid; j < N; j += THREADS) {
            float t = 0.0f;
#pragma unroll 8
            for (int k = 0; k < BPB; k++) t += g_part[blocal][k][j];
            g_C[(size_t)b * N + j] = sc[j] + __log2f(t);
        }
        __syncthreads();
        if (tid == 0) g_cnt[blocal] = 0;
    }
}

// ---------------------------------------------------------------------------
// Final: out = exp2(s - R - C), s read L2-hot from the last iteration.
// ---------------------------------------------------------------------------
__global__ void __launch_bounds__(256) gs_final(float* __restrict__ out, int b0) {
    size_t tid = (size_t)blockIdx.x * 256 + threadIdx.x;
    size_t e = (size_t)b0 * N * N + tid * 4;
    int row = (int)(e >> 10);
    int b = row >> 10;
    int j = (int)(e & (N - 1));
    float r = g_R[row];
    float4 c = *reinterpret_cast<const float4*>(g_C + (size_t)b * N + j);
    float4 sv = *reinterpret_cast<const float4*>(g_s + e);
    float4 o;
    o.x = exp2f(sv.x - r - c.x);
    o.y = exp2f(sv.y - r - c.y);
    o.z = exp2f(sv.z - r - c.z);
    o.w = exp2f(sv.w - r - c.w);
    *reinterpret_cast<float4*>(out + e) = o;
}

// ---------------------------------------------------------------------------
// 8 groups of 16 batches (64 MB of s each) keep every pass L2-resident.
// 22 launches per group instead of 42, one s-read per iteration.
// ---------------------------------------------------------------------------
extern "C" void kernel_launch(void* const* d_in, const int* in_sizes, int n_in,
                              void* d_out, int out_size) {
    const float* la = (const float*)d_in[0];
    const float* noise = (const float*)d_in[1];
    float* out = (float*)d_out;

    static int smem_set = 0;
    const int smem_bytes = (RPB * N + N + RPB + 16) * 4;   // ~69.4 KB
    if (!smem_set) {
        cudaFuncSetAttribute(gs_iter, cudaFuncAttributeMaxDynamicSharedMemorySize,
                             smem_bytes);
        smem_set = 1;
    }

    const int blk_elems = (GROUP * N * N) / (256 * 4);
    for (int g = 0; g < NGROUPS; g++) {
        int b0 = g * GROUP;
        gs_init<<<blk_elems, 256>>>(la, noise, b0);
        gs_iter<<<GROUP * BPB, THREADS, smem_bytes>>>(b0, 1);
        for (int t = 1; t < NITERS; t++)
            gs_iter<<<GROUP * BPB, THREADS, smem_bytes>>>(b0, 0);
        gs_final<<<blk_elems, 256>>>(out, b0);
    }
}

// round 4
// speedup vs baseline: 1.4258x; 1.4258x over previous
#include <cuda_runtime.h>
#include <math_constants.h>

#define NB 128
#define N 1024
#define NITERS 20
#define GROUP 16
#define NGROUPS (NB / GROUP)
#define LOG2E 1.44269504088896340736f

// s stored in LOG2 domain: s2 = (log_alpha + gumbel)/TEMP * log2(e).
// R, C are log2-domain normalizers; hot exp is a bare MUFU.EX2.
static __device__ float g_s[(size_t)NB * N * N];   // 512 MB
static __device__ float g_R[NB * N];
static __device__ float g_C[NB * N];

__device__ __forceinline__ float ex2(float x) {
    float y;
    asm("ex2.approx.ftz.f32 %0, %1;" : "=f"(y) : "f"(x));
    return y;
}

// ---------------------------------------------------------------------------
// Init: s2 = (la + gumbel)/TEMP * log2e; zero C. Accurate logf for the Gumbel
// tail (its extreme values dominate the row maxima).
// ---------------------------------------------------------------------------
__global__ void __launch_bounds__(256) gs_init(const float* __restrict__ la,
                                               const float* __restrict__ noise,
                                               int b0) {
    const float EPS = 1e-20f;
    size_t tid = (size_t)blockIdx.x * 256 + threadIdx.x;
    size_t e = (size_t)b0 * N * N + tid * 4;
    float4 a = *reinterpret_cast<const float4*>(la + e);
    float4 u = *reinterpret_cast<const float4*>(noise + e);
    const float SC = 10.0f * LOG2E;
    float4 s;
    s.x = (a.x - logf(EPS - logf(u.x + EPS))) * SC;
    s.y = (a.y - logf(EPS - logf(u.y + EPS))) * SC;
    s.z = (a.z - logf(EPS - logf(u.z + EPS))) * SC;
    s.w = (a.w - logf(EPS - logf(u.w + EPS))) * SC;
    *reinterpret_cast<float4*>(g_s + e) = s;
    if (tid < (size_t)GROUP * N) g_C[(size_t)b0 * N + tid] = 0.0f;
}

// ---------------------------------------------------------------------------
// First row pass (t=0, C=0): s unbounded -> exact per-row max.
// Warp per row, whole row front-loaded into 32 registers.
// ---------------------------------------------------------------------------
__global__ void __launch_bounds__(256) gs_row_first(int b0) {
    int lane = threadIdx.x & 31, w = threadIdx.x >> 5;
    int rglob = b0 * N + blockIdx.x * 8 + w;
    const float4* __restrict__ srow =
        reinterpret_cast<const float4*>(g_s + (size_t)rglob * N);

    float4 sv[8];
#pragma unroll
    for (int k = 0; k < 8; k++) sv[k] = srow[k * 32 + lane];
    float m = -CUDART_INF_F;
#pragma unroll
    for (int k = 0; k < 8; k++)
        m = fmaxf(m, fmaxf(fmaxf(sv[k].x, sv[k].y), fmaxf(sv[k].z, sv[k].w)));
#pragma unroll
    for (int o = 16; o; o >>= 1) m = fmaxf(m, __shfl_xor_sync(~0u, m, o));
    float a0 = 0.f, a1 = 0.f;
#pragma unroll
    for (int k = 0; k < 8; k++) {
        a0 += ex2(sv[k].x - m) + ex2(sv[k].y - m);
        a1 += ex2(sv[k].z - m) + ex2(sv[k].w - m);
    }
    float sum = a0 + a1;
#pragma unroll
    for (int o = 16; o; o >>= 1) sum += __shfl_xor_sync(~0u, sum, o);
    if (lane == 0) g_R[rglob] = m + __log2f(sum);
}

// ---------------------------------------------------------------------------
// Row pass, t>=1 (shift trick: s - C <= R_prev, all exp args <= 0).
// C_prev lives in SMEM (shared by the block's 8 rows of one batch);
// all 8 s-float4 loads front-batched -> MLP 8, half the LDG count.
// ---------------------------------------------------------------------------
__global__ void __launch_bounds__(256) gs_row(int b0) {
    __shared__ float sc[N];
    int tid = threadIdx.x, lane = tid & 31, w = tid >> 5;
    int b = b0 + (blockIdx.x >> 7);
    int row = ((blockIdx.x & 127) << 3) + w;

    reinterpret_cast<float4*>(sc)[tid] =
        reinterpret_cast<const float4*>(g_C + (size_t)b * N)[tid];
    __syncthreads();

    const float4* __restrict__ srow =
        reinterpret_cast<const float4*>(g_s + ((size_t)b * N + row) * N);
    float rprev = g_R[(size_t)b * N + row];

    float4 sv[8];
#pragma unroll
    for (int k = 0; k < 8; k++) sv[k] = srow[k * 32 + lane];

    const float4* scv = reinterpret_cast<const float4*>(sc);
    float a0 = 0.f, a1 = 0.f;
#pragma unroll
    for (int k = 0; k < 8; k++) {
        float4 cv = scv[k * 32 + lane];
        a0 += ex2(sv[k].x - cv.x - rprev) + ex2(sv[k].y - cv.y - rprev);
        a1 += ex2(sv[k].z - cv.z - rprev) + ex2(sv[k].w - cv.w - rprev);
    }
    float sum = a0 + a1;
#pragma unroll
    for (int o = 16; o; o >>= 1) sum += __shfl_xor_sync(~0u, sum, o);
    if (lane == 0) g_R[(size_t)b * N + row] = rprev + __log2f(sum);
}

// ---------------------------------------------------------------------------
// Col pass (shift trick: s - R <= C_prev, all exp args <= 0).
// 512 threads: 16 warps x 64-row stripes, 32 cols/block, R in SMEM,
// explicit 8-deep load prefetch for MLP.
// ---------------------------------------------------------------------------
__global__ void __launch_bounds__(512) gs_col(int b0) {
    __shared__ float sr[N];
    __shared__ float part[16][33];
    int tid = threadIdx.x, lane = tid & 31, w = tid >> 5;
    int b = b0 + blockIdx.y;
    int j = blockIdx.x * 32 + lane;

    if (tid < 256)
        reinterpret_cast<float4*>(sr)[tid] =
            reinterpret_cast<const float4*>(g_R + (size_t)b * N)[tid];
    __syncthreads();

    float cprev = g_C[(size_t)b * N + j];
    const float* __restrict__ sp = g_s + (size_t)b * N * N + j;
    int i0 = w * 64;

    float acc0 = 0.f, acc1 = 0.f;
#pragma unroll
    for (int ii = 0; ii < 64; ii += 8) {
        float v[8];
#pragma unroll
        for (int t = 0; t < 8; t++) v[t] = sp[(size_t)(i0 + ii + t) * N];
#pragma unroll
        for (int t = 0; t < 8; t += 2) {
            acc0 += ex2(v[t]     - sr[i0 + ii + t]     - cprev);
            acc1 += ex2(v[t + 1] - sr[i0 + ii + t + 1] - cprev);
        }
    }
    part[w][lane] = acc0 + acc1;
    __syncthreads();
    if (w == 0) {
        float t = 0.f;
#pragma unroll
        for (int k = 0; k < 16; k++) t += part[k][lane];
        g_C[(size_t)b * N + j] = cprev + __log2f(t);
    }
}

// ---------------------------------------------------------------------------
// Final: out = exp2(s - R - C), s L2-hot from the last col pass.
// ---------------------------------------------------------------------------
__global__ void __launch_bounds__(256) gs_final(float* __restrict__ out, int b0) {
    size_t tid = (size_t)blockIdx.x * 256 + threadIdx.x;
    size_t e = (size_t)b0 * N * N + tid * 4;
    int row = (int)(e >> 10);
    int b = row >> 10;
    int j = (int)(e & (N - 1));
    float r = g_R[row];
    float4 c = *reinterpret_cast<const float4*>(g_C + (size_t)b * N + j);
    float4 sv = *reinterpret_cast<const float4*>(g_s + e);
    float4 o;
    o.x = ex2(sv.x - r - c.x);
    o.y = ex2(sv.y - r - c.y);
    o.z = ex2(sv.z - r - c.z);
    o.w = ex2(sv.w - r - c.w);
    *reinterpret_cast<float4*>(out + e) = o;
}

// ---------------------------------------------------------------------------
// 8 groups of 16 batches (64 MB of s each) keep all passes L2-resident.
// ---------------------------------------------------------------------------
extern "C" void kernel_launch(void* const* d_in, const int* in_sizes, int n_in,
                              void* d_out, int out_size) {
    const float* la = (const float*)d_in[0];
    const float* noise = (const float*)d_in[1];
    float* out = (float*)d_out;

    const int blk_elems = (GROUP * N * N) / (256 * 4);
    for (int g = 0; g < NGROUPS; g++) {
        int b0 = g * GROUP;
        gs_init<<<blk_elems, 256>>>(la, noise, b0);
        gs_row_first<<<(GROUP * N) / 8, 256>>>(b0);
        gs_col<<<dim3(N / 32, GROUP), 512>>>(b0);
        for (int t = 1; t < NITERS; t++) {
            gs_row<<<(GROUP * N) / 8, 256>>>(b0);
            gs_col<<<dim3(N / 32, GROUP), 512>>>(b0);
        }
        gs_final<<<blk_elems, 256>>>(out, b0);
    }
}